// round 17
// baseline (speedup 1.0000x reference)
#include <cuda_runtime.h>
#include <cuda_bf16.h>
#include <cstdint>
#include <math.h>

// Problem constants
#define BB 64
#define SS 512
#define II 512
#define HH 512
#define LL 2
#define MROWS (BB * LL)
#define MX (BB * SS)

// ---------------- scratch (static device memory; no allocs allowed) ----------
__device__ float g_xa[(size_t)MX * HH];       // 64 MB: xa = x @ W_ih^T + b_ih

// h exchange in MMA b-fragment layout, tf32 bits, double buffered:
// g_fb[buf][rb][ ks_g*64 + sel*32 + lane ],  ks_g = h_col>>3, sel = (h_col&7)>>2,
// lane = row*4 + (h_col&3).  16 KB per (buf, rb).
__device__ unsigned g_fb[2][16][64 * 64];

// per-CTA monotonic step flags
__device__ __align__(32) unsigned g_sf[16][8];

__device__ __forceinline__ unsigned cvt_tf32(float f) {
    unsigned u;
    asm("cvt.rna.tf32.f32 %0, %1;" : "=r"(u) : "f"(f));
    return u;
}
__device__ __forceinline__ unsigned ldcg_u32(const unsigned* p) {
    unsigned u;
    asm volatile("ld.global.cg.u32 %0, [%1];" : "=r"(u) : "l"(p));
    return u;
}

// =============================================================================
// Kernel R: reset step flags (graph-replay safety)
// =============================================================================
__global__ void reset_flags_kernel()
{
    if (threadIdx.x < 128)
        ((unsigned*)g_sf)[threadIdx.x] = 0u;
}

// =============================================================================
// Kernel A v2 (round-13, proven): staged tf32 mma GEMM, 128x128, k-chunk 16.
// =============================================================================
#define CH 16
#define APAD 17

__global__ void __launch_bounds__(256) gemm_xa_mma_kernel(
    const float* __restrict__ X,      // [MX][II]
    const float* __restrict__ Wih,    // [HH][II]
    const float* __restrict__ bias)   // [HH]
{
    __shared__ unsigned As[2][128 * APAD];
    __shared__ unsigned Bs[2][128 * APAD];

    const int m0   = blockIdx.y * 128;
    const int n0   = blockIdx.x * 128;
    const int tid  = threadIdx.x;
    const int w    = tid >> 5;
    const int lane = tid & 31;
    const int g    = lane >> 2;
    const int t    = lane & 3;
    const int wr   = w >> 2;
    const int wc   = w & 3;

    const int srow = tid >> 1;
    const int skq  = (tid & 1) * 8;

    const float* Ag = X   + (size_t)(m0 + srow) * II + skq;
    const float* Bg = Wih + (size_t)(n0 + srow) * II + skq;

    float acc[4][4][4];
#pragma unroll
    for (int mf = 0; mf < 4; mf++)
#pragma unroll
        for (int nf = 0; nf < 4; nf++)
#pragma unroll
            for (int r = 0; r < 4; r++) acc[mf][nf][r] = 0.f;

    {
        const float4 av0 = *(const float4*)(Ag + 0);
        const float4 av1 = *(const float4*)(Ag + 4);
        const float4 bv0 = *(const float4*)(Bg + 0);
        const float4 bv1 = *(const float4*)(Bg + 4);
        unsigned* ad = &As[0][srow * APAD + skq];
        unsigned* bd = &Bs[0][srow * APAD + skq];
        ad[0] = cvt_tf32(av0.x); ad[1] = cvt_tf32(av0.y);
        ad[2] = cvt_tf32(av0.z); ad[3] = cvt_tf32(av0.w);
        ad[4] = cvt_tf32(av1.x); ad[5] = cvt_tf32(av1.y);
        ad[6] = cvt_tf32(av1.z); ad[7] = cvt_tf32(av1.w);
        bd[0] = cvt_tf32(bv0.x); bd[1] = cvt_tf32(bv0.y);
        bd[2] = cvt_tf32(bv0.z); bd[3] = cvt_tf32(bv0.w);
        bd[4] = cvt_tf32(bv1.x); bd[5] = cvt_tf32(bv1.y);
        bd[6] = cvt_tf32(bv1.z); bd[7] = cvt_tf32(bv1.w);
    }
    __syncthreads();

    const int abase0 = (wr * 64 + g) * APAD + t;
    const int bbase0 = (wc * 32 + g) * APAD + t;

    for (int c = 0; c < 32; c++) {
        float4 av0, av1, bv0, bv1;
        const bool more = (c < 31);
        if (more) {
            const int kc = (c + 1) * CH;
            av0 = *(const float4*)(Ag + kc);
            av1 = *(const float4*)(Ag + kc + 4);
            bv0 = *(const float4*)(Bg + kc);
            bv1 = *(const float4*)(Bg + kc + 4);
        }

        const unsigned* Ab = As[c & 1];
        const unsigned* Bb = Bs[c & 1];
#pragma unroll
        for (int ks = 0; ks < 2; ks++) {
            const int ko = ks * 8;
            unsigned af[4][4];
#pragma unroll
            for (int mf = 0; mf < 4; mf++) {
                const int base = abase0 + mf * 16 * APAD + ko;
                af[mf][0] = Ab[base];
                af[mf][1] = Ab[base + 8 * APAD];
                af[mf][2] = Ab[base + 4];
                af[mf][3] = Ab[base + 8 * APAD + 4];
            }
            unsigned bf[4][2];
#pragma unroll
            for (int nf = 0; nf < 4; nf++) {
                const int base = bbase0 + nf * 8 * APAD + ko;
                bf[nf][0] = Bb[base];
                bf[nf][1] = Bb[base + 4];
            }
#pragma unroll
            for (int mf = 0; mf < 4; mf++)
#pragma unroll
                for (int nf = 0; nf < 4; nf++) {
                    asm volatile(
                        "mma.sync.aligned.m16n8k8.row.col.f32.tf32.tf32.f32 "
                        "{%0,%1,%2,%3}, {%4,%5,%6,%7}, {%8,%9}, {%0,%1,%2,%3};"
                        : "+f"(acc[mf][nf][0]), "+f"(acc[mf][nf][1]),
                          "+f"(acc[mf][nf][2]), "+f"(acc[mf][nf][3])
                        : "r"(af[mf][0]), "r"(af[mf][1]),
                          "r"(af[mf][2]), "r"(af[mf][3]),
                          "r"(bf[nf][0]), "r"(bf[nf][1]));
                }
        }

        if (more) {
            unsigned* ad = &As[(c + 1) & 1][srow * APAD + skq];
            unsigned* bd = &Bs[(c + 1) & 1][srow * APAD + skq];
            ad[0] = cvt_tf32(av0.x); ad[1] = cvt_tf32(av0.y);
            ad[2] = cvt_tf32(av0.z); ad[3] = cvt_tf32(av0.w);
            ad[4] = cvt_tf32(av1.x); ad[5] = cvt_tf32(av1.y);
            ad[6] = cvt_tf32(av1.z); ad[7] = cvt_tf32(av1.w);
            bd[0] = cvt_tf32(bv0.x); bd[1] = cvt_tf32(bv0.y);
            bd[2] = cvt_tf32(bv0.z); bd[3] = cvt_tf32(bv0.w);
            bd[4] = cvt_tf32(bv1.x); bd[5] = cvt_tf32(bv1.y);
            bd[6] = cvt_tf32(bv1.z); bd[7] = cvt_tf32(bv1.w);
            __syncthreads();
        }
    }

    const int mbase = m0 + wr * 64;
    const int nbase = n0 + wc * 32;
#pragma unroll
    for (int nf = 0; nf < 4; nf++) {
        const int col = nbase + nf * 8 + 2 * t;
        const float2 bv = *(const float2*)&bias[col];
#pragma unroll
        for (int mf = 0; mf < 4; mf++) {
            const int row0 = mbase + mf * 16 + g;
            float2 d01, d23;
            d01.x = acc[mf][nf][0] + bv.x;
            d01.y = acc[mf][nf][1] + bv.y;
            d23.x = acc[mf][nf][2] + bv.x;
            d23.y = acc[mf][nf][3] + bv.y;
            *(float2*)&g_xa[(size_t)row0 * HH + col]       = d01;
            *(float2*)&g_xa[(size_t)(row0 + 8) * HH + col] = d23;
        }
    }
}

// =============================================================================
// Kernel B v9.1: tensor recurrence, fragment-layout L2 exchange.
// (round-14 design with the A3-chain out-of-bounds index FIXED:
//  bbB[2*(ks+8)] pairs slices 24..31 with wa[ks+24].)
// =============================================================================
#define GB_CTAS 128

__global__ void __launch_bounds__(256, 1) rnn_persistent_kernel(
    const float* __restrict__ W_hh,   // [HH][HH]
    const float* __restrict__ b_hh,   // [HH]
    float* __restrict__ out)          // y then h_last
{
    __shared__ float red[2 * 64 * 8];     // [kw][m][n]

    const int tid  = threadIdx.x;
    const int w    = tid >> 5;
    const int lane = tid & 31;
    const int g    = lane >> 2;
    const int t    = lane & 3;
    const int mw   = w & 3;
    const int kw   = w >> 2;
    const int kb   = kw * 256;

    const int gb  = blockIdx.x & 7;
    const int rb  = blockIdx.x >> 3;
    const int g0  = gb * 64;
    const int row_base = rb * 8;

    // one-time: W A-fragments into registers
    unsigned wa[32][4];
    {
        const float* w0p = W_hh + (size_t)(g0 + mw * 16 + g) * HH + kb;
        const float* w1p = w0p + 8 * HH;
#pragma unroll
        for (int ks = 0; ks < 32; ks++) {
            wa[ks][0] = cvt_tf32(__ldg(w0p + ks * 8 + t));
            wa[ks][1] = cvt_tf32(__ldg(w1p + ks * 8 + t));
            wa[ks][2] = cvt_tf32(__ldg(w0p + ks * 8 + t + 4));
            wa[ks][3] = cvt_tf32(__ldg(w1p + ks * 8 + t + 4));
        }
    }

    // epilogue mapping: outputs (n=orow, m=oc, oc+1)
    const int orow  = tid >> 5;
    const int oc    = 2 * (tid & 31);
    const int grow  = row_base + orow;
    const int b_idx = grow >> 1;
    const int l_idx = grow & 1;
    const int gcol  = g0 + oc;

    // fragment-store indices for this thread's two outputs
    const int c0i = (gcol >> 3) * 64 + (((gcol >> 2) & 1) << 5) + orow * 4 + (gcol & 3);
    const int c1  = gcol + 1;
    const int c1i = (c1 >> 3) * 64 + (((c1 >> 2) & 1) << 5) + orow * 4 + (c1 & 3);

    const float2 bg  = *(const float2*)&b_hh[gcol];
    float2 xav = *(const float2*)&g_xa[((size_t)b_idx * SS + 0) * HH + gcol];

    unsigned* my_flag = &g_sf[rb][gb];
    const unsigned* gflags = &g_sf[rb][0];

    const size_t Y_ELEMS = (size_t)BB * SS * LL * HH;
    __syncthreads();

    for (int s = 0; s < SS; s++) {
        float v0, v1;
        if (s == 0) {
            v0 = tanhf(xav.x + bg.x);
            v1 = tanhf(xav.y + bg.y);
        } else {
            // wait until all 8 group CTAs have published step s
            if (tid == 0) {
                const unsigned target = (unsigned)s;
                bool ok;
                do {
                    unsigned f[8];
#pragma unroll
                    for (int p = 0; p < 8; p++)
                        asm volatile("ld.relaxed.gpu.u32 %0, [%1];"
                                     : "=r"(f[p]) : "l"(gflags + p));
                    ok = true;
#pragma unroll
                    for (int p = 0; p < 8; p++) ok &= (f[p] >= target);
                } while (!ok);
                asm volatile("fence.acq_rel.gpu;" ::: "memory");
            }
            __syncthreads();

            // fragments straight from L2 (lane-contiguous, .cg)
            const unsigned* fb = &g_fb[s & 1][rb][0] + kw * 32 * 64 + lane;

            float A0[4] = {0.f, 0.f, 0.f, 0.f};
            float A1[4] = {0.f, 0.f, 0.f, 0.f};
            float A2[4] = {0.f, 0.f, 0.f, 0.f};
            float A3[4] = {0.f, 0.f, 0.f, 0.f};

            unsigned bbA[32];
#pragma unroll
            for (int ks = 0; ks < 16; ks++) {
                bbA[2 * ks]     = ldcg_u32(fb + ks * 64);
                bbA[2 * ks + 1] = ldcg_u32(fb + ks * 64 + 32);
            }
#pragma unroll
            for (int ks = 0; ks < 8; ks++) {
                asm volatile(
                    "mma.sync.aligned.m16n8k8.row.col.f32.tf32.tf32.f32 "
                    "{%0,%1,%2,%3}, {%4,%5,%6,%7}, {%8,%9}, {%0,%1,%2,%3};"
                    : "+f"(A0[0]), "+f"(A0[1]), "+f"(A0[2]), "+f"(A0[3])
                    : "r"(wa[ks][0]), "r"(wa[ks][1]),
                      "r"(wa[ks][2]), "r"(wa[ks][3]),
                      "r"(bbA[2 * ks]), "r"(bbA[2 * ks + 1]));
                asm volatile(
                    "mma.sync.aligned.m16n8k8.row.col.f32.tf32.tf32.f32 "
                    "{%0,%1,%2,%3}, {%4,%5,%6,%7}, {%8,%9}, {%0,%1,%2,%3};"
                    : "+f"(A1[0]), "+f"(A1[1]), "+f"(A1[2]), "+f"(A1[3])
                    : "r"(wa[ks + 8][0]), "r"(wa[ks + 8][1]),
                      "r"(wa[ks + 8][2]), "r"(wa[ks + 8][3]),
                      "r"(bbA[2 * (ks + 8)]), "r"(bbA[2 * (ks + 8) + 1]));
            }

            unsigned bbB[32];
#pragma unroll
            for (int ks = 0; ks < 16; ks++) {
                bbB[2 * ks]     = ldcg_u32(fb + (ks + 16) * 64);
                bbB[2 * ks + 1] = ldcg_u32(fb + (ks + 16) * 64 + 32);
            }
#pragma unroll
            for (int ks = 0; ks < 8; ks++) {
                asm volatile(
                    "mma.sync.aligned.m16n8k8.row.col.f32.tf32.tf32.f32 "
                    "{%0,%1,%2,%3}, {%4,%5,%6,%7}, {%8,%9}, {%0,%1,%2,%3};"
                    : "+f"(A2[0]), "+f"(A2[1]), "+f"(A2[2]), "+f"(A2[3])
                    : "r"(wa[ks + 16][0]), "r"(wa[ks + 16][1]),
                      "r"(wa[ks + 16][2]), "r"(wa[ks + 16][3]),
                      "r"(bbB[2 * ks]), "r"(bbB[2 * ks + 1]));
                asm volatile(
                    "mma.sync.aligned.m16n8k8.row.col.f32.tf32.tf32.f32 "
                    "{%0,%1,%2,%3}, {%4,%5,%6,%7}, {%8,%9}, {%0,%1,%2,%3};"
                    : "+f"(A3[0]), "+f"(A3[1]), "+f"(A3[2]), "+f"(A3[3])
                    : "r"(wa[ks + 24][0]), "r"(wa[ks + 24][1]),
                      "r"(wa[ks + 24][2]), "r"(wa[ks + 24][3]),
                      "r"(bbB[2 * (ks + 8)]), "r"(bbB[2 * (ks + 8) + 1]));
            }

            const float a0 = (A0[0] + A1[0]) + (A2[0] + A3[0]);
            const float a1 = (A0[1] + A1[1]) + (A2[1] + A3[1]);
            const float a2 = (A0[2] + A1[2]) + (A2[2] + A3[2]);
            const float a3 = (A0[3] + A1[3]) + (A2[3] + A3[3]);

            // k-half reduce through smem
            {
                float* rp = red + kw * 512;
                *(float2*)&rp[(mw * 16 + g) * 8 + 2 * t]     = make_float2(a0, a1);
                *(float2*)&rp[(mw * 16 + g + 8) * 8 + 2 * t] = make_float2(a2, a3);
            }
            __syncthreads();

            const float s0 = red[oc * 8 + orow]       + red[512 + oc * 8 + orow];
            const float s1 = red[(oc + 1) * 8 + orow] + red[512 + (oc + 1) * 8 + orow];
            v0 = tanhf(s0 + xav.x + bg.x);
            v1 = tanhf(s1 + xav.y + bg.y);
        }

        if (s < SS - 1) {
            // publish fragments for step s+1 (pre-converted to tf32)
            unsigned* dst = &g_fb[(s + 1) & 1][rb][0];
            const unsigned u0 = cvt_tf32(v0);
            const unsigned u1 = cvt_tf32(v1);
            asm volatile("st.global.cg.u32 [%0], %1;" :: "l"(dst + c0i), "r"(u0));
            asm volatile("st.global.cg.u32 [%0], %1;" :: "l"(dst + c1i), "r"(u1));
            __syncthreads();
            if (tid == 0)
                asm volatile("st.release.gpu.u32 [%0], %1;"
                             :: "l"(my_flag), "r"((unsigned)(s + 1)));
        }

        // epilogue (overlaps peers' polls): y writes + next xa prefetch
        {
            float2 yv; yv.x = v0; yv.y = v1;
            *(float2*)&out[(((size_t)b_idx * SS + s) * LL + l_idx) * HH + gcol] = yv;
            if (s == SS - 1) {
                out[Y_ELEMS + (size_t)grow * HH + gcol]     = v0;
                out[Y_ELEMS + (size_t)grow * HH + gcol + 1] = v1;
            } else {
                xav = *(const float2*)&g_xa[((size_t)b_idx * SS + (s + 1)) * HH + gcol];
            }
        }
    }
}

// =============================================================================
// launch
// =============================================================================
extern "C" void kernel_launch(void* const* d_in, const int* in_sizes, int n_in,
                              void* d_out, int out_size)
{
    const float* x    = (const float*)d_in[0];
    const float* W_ih = (const float*)d_in[1];
    const float* b_ih = (const float*)d_in[2];
    const float* W_hh = (const float*)d_in[3];
    const float* b_hh = (const float*)d_in[4];
    float* out = (float*)d_out;

    reset_flags_kernel<<<1, 128>>>();

    dim3 gridA(HH / 128, MX / 128);   // (4, 256)
    gemm_xa_mma_kernel<<<gridA, 256>>>(x, W_ih, b_ih);

    rnn_persistent_kernel<<<GB_CTAS, 256>>>(W_hh, b_hh, out);
}